// round 2
// baseline (speedup 1.0000x reference)
#include <cuda_runtime.h>
#include <cstdint>

// Problem constants
#define B_ 4
#define T_ 1024
#define E_ 1024
#define H_ 16
#define D_ 64
#define M_ (B_*T_)          // 4096 rows of activations
#define SCALE_ 0.125f       // 1/sqrt(64)
#define WEPS_ 1e-5f

// Scratch (allocation-free rule: __device__ globals)
__device__ float g_qh[B_*H_*T_*D_];            // [B,H,T,D] 16 MB
__device__ float g_kh[B_*H_*T_*D_];
__device__ float g_vh[B_*H_*T_*D_];
__device__ float g_att[B_*H_*T_*D_];
__device__ float g_S[(size_t)B_*H_*T_*T_];     // [B*H, T, T] 256 MB

__device__ __forceinline__ float neg_inf() { return __int_as_float(0xff800000); }

// ---------------------------------------------------------------------------
// Projection: Out[b,h,t,d] = sum_e X[b,t,e] * W[h*64+d, e] + bias[h*64+d]
// NT GEMM M=4096 N=1024 K=1024, output scattered into head layout.
// Tiles 128x128x16, 256 threads, 8x8 per-thread micro-tile.
// ---------------------------------------------------------------------------
__global__ void __launch_bounds__(256, 2) proj_kernel(
    const float* __restrict__ X, const float* __restrict__ W,
    const float* __restrict__ bias, int which)
{
    __shared__ float As[16][128];   // [k][m] transposed
    __shared__ float Bs[16][128];   // [k][n] transposed
    const int m0 = blockIdx.y * 128;
    const int n0 = blockIdx.x * 128;
    const int tid = threadIdx.x;
    const int tx = tid & 15, ty = tid >> 4;

    float acc[8][8];
    #pragma unroll
    for (int i = 0; i < 8; i++)
        #pragma unroll
        for (int j = 0; j < 8; j++) acc[i][j] = 0.0f;

    for (int k0 = 0; k0 < E_; k0 += 16) {
        #pragma unroll
        for (int i = 0; i < 2; i++) {
            int f = tid + i * 256;         // 512 float4 per operand tile
            int row = f >> 2;
            int c4  = (f & 3) * 4;
            float4 a = *(const float4*)&X[(size_t)(m0 + row) * E_ + k0 + c4];
            As[c4 + 0][row] = a.x; As[c4 + 1][row] = a.y;
            As[c4 + 2][row] = a.z; As[c4 + 3][row] = a.w;
            float4 b = *(const float4*)&W[(size_t)(n0 + row) * E_ + k0 + c4];
            Bs[c4 + 0][row] = b.x; Bs[c4 + 1][row] = b.y;
            Bs[c4 + 2][row] = b.z; Bs[c4 + 3][row] = b.w;
        }
        __syncthreads();
        #pragma unroll
        for (int k = 0; k < 16; k++) {
            float4 a0 = *(const float4*)&As[k][ty * 8];
            float4 a1 = *(const float4*)&As[k][ty * 8 + 4];
            float4 b0 = *(const float4*)&Bs[k][tx * 8];
            float4 b1 = *(const float4*)&Bs[k][tx * 8 + 4];
            float av[8] = {a0.x, a0.y, a0.z, a0.w, a1.x, a1.y, a1.z, a1.w};
            float bv[8] = {b0.x, b0.y, b0.z, b0.w, b1.x, b1.y, b1.z, b1.w};
            #pragma unroll
            for (int i = 0; i < 8; i++)
                #pragma unroll
                for (int j = 0; j < 8; j++)
                    acc[i][j] = fmaf(av[i], bv[j], acc[i][j]);
        }
        __syncthreads();
    }

    float* Out = (which == 0) ? g_qh : (which == 1) ? g_kh : g_vh;
    #pragma unroll
    for (int j = 0; j < 8; j++) {
        int n = n0 + tx * 8 + j;
        float bv = bias[n];
        int h = n >> 6, d = n & 63;
        #pragma unroll
        for (int i = 0; i < 8; i++) {
            int m = m0 + ty * 8 + i;
            int bb = m >> 10, t = m & 1023;
            Out[(((bb * H_) + h) * T_ + t) * D_ + d] = acc[i][j] + bv;
        }
    }
}

// ---------------------------------------------------------------------------
// Energy: S[head,i,j] = mask(sum_d qh[i,d]*kh[j,d] * SCALE * w_j^2)
// Per-head NT GEMM, K=64. grid (8, 8, 64 heads).
// ---------------------------------------------------------------------------
__global__ void __launch_bounds__(256, 2) energy_kernel(const float* __restrict__ weights)
{
    __shared__ float As[16][128];
    __shared__ float Bs[16][128];
    const int head = blockIdx.z;
    const float* A = g_qh + head * T_ * D_;
    const float* Bm = g_kh + head * T_ * D_;
    const int m0 = blockIdx.y * 128;
    const int n0 = blockIdx.x * 128;
    const int tid = threadIdx.x;
    const int tx = tid & 15, ty = tid >> 4;

    float acc[8][8];
    #pragma unroll
    for (int i = 0; i < 8; i++)
        #pragma unroll
        for (int j = 0; j < 8; j++) acc[i][j] = 0.0f;

    for (int k0 = 0; k0 < D_; k0 += 16) {
        #pragma unroll
        for (int i = 0; i < 2; i++) {
            int f = tid + i * 256;
            int row = f >> 2;
            int c4  = (f & 3) * 4;
            float4 a = *(const float4*)&A[(m0 + row) * D_ + k0 + c4];
            As[c4 + 0][row] = a.x; As[c4 + 1][row] = a.y;
            As[c4 + 2][row] = a.z; As[c4 + 3][row] = a.w;
            float4 b = *(const float4*)&Bm[(n0 + row) * D_ + k0 + c4];
            Bs[c4 + 0][row] = b.x; Bs[c4 + 1][row] = b.y;
            Bs[c4 + 2][row] = b.z; Bs[c4 + 3][row] = b.w;
        }
        __syncthreads();
        #pragma unroll
        for (int k = 0; k < 16; k++) {
            float4 a0 = *(const float4*)&As[k][ty * 8];
            float4 a1 = *(const float4*)&As[k][ty * 8 + 4];
            float4 b0 = *(const float4*)&Bs[k][tx * 8];
            float4 b1 = *(const float4*)&Bs[k][tx * 8 + 4];
            float av[8] = {a0.x, a0.y, a0.z, a0.w, a1.x, a1.y, a1.z, a1.w};
            float bv[8] = {b0.x, b0.y, b0.z, b0.w, b1.x, b1.y, b1.z, b1.w};
            #pragma unroll
            for (int i = 0; i < 8; i++)
                #pragma unroll
                for (int j = 0; j < 8; j++)
                    acc[i][j] = fmaf(av[i], bv[j], acc[i][j]);
        }
        __syncthreads();
    }

    const float* wrow = weights + (head >> 4) * T_;   // batch = head/H
    float* Srow = g_S + (size_t)head * T_ * T_;
    #pragma unroll
    for (int j = 0; j < 8; j++) {
        int n = n0 + tx * 8 + j;
        float w = wrow[n];
        bool masked = (w < WEPS_);
        float scl = SCALE_ * w * w;
        #pragma unroll
        for (int i = 0; i < 8; i++) {
            int m = m0 + ty * 8 + i;
            Srow[(size_t)m * T_ + n] = masked ? neg_inf() : acc[i][j] * scl;
        }
    }
}

// ---------------------------------------------------------------------------
// Row softmax over g_S: 65536 rows of 1024. One CTA (256 threads) per row.
// ---------------------------------------------------------------------------
__global__ void softmax_kernel()
{
    const size_t row = blockIdx.x;
    float* r = g_S + row * T_;
    const int tid = threadIdx.x;
    __shared__ float red[256];

    float4 x = *(const float4*)&r[tid * 4];
    float m = fmaxf(fmaxf(x.x, x.y), fmaxf(x.z, x.w));
    red[tid] = m; __syncthreads();
    #pragma unroll
    for (int s = 128; s > 0; s >>= 1) {
        if (tid < s) red[tid] = fmaxf(red[tid], red[tid + s]);
        __syncthreads();
    }
    float rmax = red[0];
    __syncthreads();

    float e0 = __expf(x.x - rmax);
    float e1 = __expf(x.y - rmax);
    float e2 = __expf(x.z - rmax);
    float e3 = __expf(x.w - rmax);
    red[tid] = e0 + e1 + e2 + e3; __syncthreads();
    #pragma unroll
    for (int s = 128; s > 0; s >>= 1) {
        if (tid < s) red[tid] = red[tid] + red[tid + s];
        __syncthreads();
    }
    float inv = 1.0f / red[0];

    float4 o = make_float4(e0 * inv, e1 * inv, e2 * inv, e3 * inv);
    *(float4*)&r[tid * 4] = o;
}

// ---------------------------------------------------------------------------
// PV: att[head,q,d] = sum_k S[head,q,k] * vh[head,k,d]   (NN GEMM, N=64)
// Tiles 128x64x16, 256 threads, 8x4 micro-tile. grid (8 mtiles, 64 heads)
// ---------------------------------------------------------------------------
__global__ void __launch_bounds__(256, 2) pv_kernel()
{
    __shared__ float As[16][128];   // [k][m]
    __shared__ float Bs[16][64];    // [k][d]
    const int head = blockIdx.y;
    const float* S = g_S + (size_t)head * T_ * T_;
    const float* V = g_vh + head * T_ * D_;
    const int m0 = blockIdx.x * 128;
    const int tid = threadIdx.x;
    const int tx = tid & 15, ty = tid >> 4;

    float acc[8][4];
    #pragma unroll
    for (int i = 0; i < 8; i++)
        #pragma unroll
        for (int j = 0; j < 4; j++) acc[i][j] = 0.0f;

    for (int k0 = 0; k0 < T_; k0 += 16) {
        #pragma unroll
        for (int i = 0; i < 2; i++) {
            int f = tid + i * 256;
            int row = f >> 2;
            int c4  = (f & 3) * 4;
            float4 a = *(const float4*)&S[(size_t)(m0 + row) * T_ + k0 + c4];
            As[c4 + 0][row] = a.x; As[c4 + 1][row] = a.y;
            As[c4 + 2][row] = a.z; As[c4 + 3][row] = a.w;
        }
        {
            int row = tid >> 4;          // 0..15 (k)
            int c4  = (tid & 15) * 4;    // 0..60 (d)
            *(float4*)&Bs[row][c4] = *(const float4*)&V[(k0 + row) * D_ + c4];
        }
        __syncthreads();
        #pragma unroll
        for (int k = 0; k < 16; k++) {
            float4 a0 = *(const float4*)&As[k][ty * 8];
            float4 a1 = *(const float4*)&As[k][ty * 8 + 4];
            float4 b  = *(const float4*)&Bs[k][tx * 4];
            float av[8] = {a0.x, a0.y, a0.z, a0.w, a1.x, a1.y, a1.z, a1.w};
            float bv[4] = {b.x, b.y, b.z, b.w};
            #pragma unroll
            for (int i = 0; i < 8; i++)
                #pragma unroll
                for (int j = 0; j < 4; j++)
                    acc[i][j] = fmaf(av[i], bv[j], acc[i][j]);
        }
        __syncthreads();
    }

    float* O = g_att + head * T_ * D_;
    #pragma unroll
    for (int i = 0; i < 8; i++) {
        int m = m0 + ty * 8 + i;
        #pragma unroll
        for (int j = 0; j < 4; j++)
            O[m * D_ + tx * 4 + j] = acc[i][j];
    }
}

// ---------------------------------------------------------------------------
// Output projection: out[m,n] = sum_k att_flat[m,k]*Wo[n,k] + bo[n]
// att_flat gathered on the fly from head layout.
// ---------------------------------------------------------------------------
__global__ void __launch_bounds__(256, 2) outproj_kernel(
    const float* __restrict__ Wo, const float* __restrict__ bo,
    float* __restrict__ out)
{
    __shared__ float As[16][128];
    __shared__ float Bs[16][128];
    const int m0 = blockIdx.y * 128;
    const int n0 = blockIdx.x * 128;
    const int tid = threadIdx.x;
    const int tx = tid & 15, ty = tid >> 4;

    float acc[8][8];
    #pragma unroll
    for (int i = 0; i < 8; i++)
        #pragma unroll
        for (int j = 0; j < 8; j++) acc[i][j] = 0.0f;

    for (int k0 = 0; k0 < E_; k0 += 16) {
        #pragma unroll
        for (int i = 0; i < 2; i++) {
            int f = tid + i * 256;
            int row = f >> 2;
            int c4  = (f & 3) * 4;
            int k = k0 + c4;                 // 4 contiguous elems stay in one head chunk
            int m = m0 + row;
            int bb = m >> 10, t = m & 1023;
            int h = k >> 6, d = k & 63;
            float4 a = *(const float4*)&g_att[(((bb * H_) + h) * T_ + t) * D_ + d];
            As[c4 + 0][row] = a.x; As[c4 + 1][row] = a.y;
            As[c4 + 2][row] = a.z; As[c4 + 3][row] = a.w;
            float4 b = *(const float4*)&Wo[(size_t)(n0 + row) * E_ + k0 + c4];
            Bs[c4 + 0][row] = b.x; Bs[c4 + 1][row] = b.y;
            Bs[c4 + 2][row] = b.z; Bs[c4 + 3][row] = b.w;
        }
        __syncthreads();
        #pragma unroll
        for (int k = 0; k < 16; k++) {
            float4 a0 = *(const float4*)&As[k][ty * 8];
            float4 a1 = *(const float4*)&As[k][ty * 8 + 4];
            float4 b0 = *(const float4*)&Bs[k][tx * 8];
            float4 b1 = *(const float4*)&Bs[k][tx * 8 + 4];
            float av[8] = {a0.x, a0.y, a0.z, a0.w, a1.x, a1.y, a1.z, a1.w};
            float bv[8] = {b0.x, b0.y, b0.z, b0.w, b1.x, b1.y, b1.z, b1.w};
            #pragma unroll
            for (int i = 0; i < 8; i++)
                #pragma unroll
                for (int j = 0; j < 8; j++)
                    acc[i][j] = fmaf(av[i], bv[j], acc[i][j]);
        }
        __syncthreads();
    }

    #pragma unroll
    for (int j = 0; j < 8; j++) {
        int n = n0 + tx * 8 + j;
        float bv = bo[n];
        #pragma unroll
        for (int i = 0; i < 8; i++) {
            int m = m0 + ty * 8 + i;
            out[(size_t)m * E_ + n] = acc[i][j] + bv;
        }
    }
}

// ---------------------------------------------------------------------------
extern "C" void kernel_launch(void* const* d_in, const int* in_sizes, int n_in,
                              void* d_out, int out_size)
{
    const float* q       = (const float*)d_in[0];
    const float* k       = (const float*)d_in[1];
    const float* v       = (const float*)d_in[2];
    const float* weights = (const float*)d_in[3];
    const float* Wq      = (const float*)d_in[4];
    const float* bq      = (const float*)d_in[5];
    const float* Wk      = (const float*)d_in[6];
    const float* bk      = (const float*)d_in[7];
    const float* Wv      = (const float*)d_in[8];
    const float* bv      = (const float*)d_in[9];
    const float* Wo      = (const float*)d_in[10];
    const float* bo      = (const float*)d_in[11];
    float* out = (float*)d_out;

    dim3 blk(256);
    proj_kernel<<<dim3(8, 32), blk>>>(q, Wq, bq, 0);
    proj_kernel<<<dim3(8, 32), blk>>>(k, Wk, bk, 1);
    proj_kernel<<<dim3(8, 32), blk>>>(v, Wv, bv, 2);
    energy_kernel<<<dim3(8, 8, 64), blk>>>(weights);
    softmax_kernel<<<dim3(B_ * H_ * T_), blk>>>();
    pv_kernel<<<dim3(8, 64), blk>>>();
    outproj_kernel<<<dim3(8, 32), blk>>>(Wo, bo, out);
}

// round 5
// speedup vs baseline: 1.4721x; 1.4721x over previous
#include <cuda_runtime.h>
#include <cuda_bf16.h>
#include <cstdint>

// ---------------- Problem constants ----------------
#define B_ 4
#define T_ 1024
#define E_ 1024
#define H_ 16
#define D_ 64
#define M_ 4096              // B*T rows
#define SCALE_ 0.125f        // 1/sqrt(64)
#define WEPS_ 1e-5f

// ---------------- Scratch (__device__ globals; no allocs allowed) ----------
__device__ __align__(16) float g_qh[B_*H_*T_*D_];
__device__ __align__(16) float g_kh[B_*H_*T_*D_];
__device__ __align__(16) float g_vh[B_*H_*T_*D_];
__device__ __align__(16) float g_att[B_*H_*T_*D_];
__device__ __align__(16) float g_S[(size_t)B_*H_*T_*T_];         // 256 MB
__device__ __align__(16) __nv_bfloat16 g_ahi[M_*E_];
__device__ __align__(16) __nv_bfloat16 g_alo[M_*E_];
__device__ __align__(16) __nv_bfloat16 g_bhi[E_*E_];
__device__ __align__(16) __nv_bfloat16 g_blo[E_*E_];

__device__ __forceinline__ float neg_inf() { return __int_as_float(0xff800000); }

__device__ __forceinline__ uint32_t smem_u32(const void* p) {
    uint32_t a;
    asm("{ .reg .u64 t; cvta.to.shared.u64 t, %1; cvt.u32.u64 %0, t; }" : "=r"(a) : "l"(p));
    return a;
}
__device__ __forceinline__ void cp16(uint32_t dst, const void* src) {
    asm volatile("cp.async.ca.shared.global [%0], [%1], 16;" :: "r"(dst), "l"(src));
}
#define CP_COMMIT() asm volatile("cp.async.commit_group;" ::: "memory")

__device__ __forceinline__ void ldsm_x4(uint32_t* r, uint32_t addr) {
    asm volatile("ldmatrix.sync.aligned.m8n8.x4.shared.b16 {%0,%1,%2,%3}, [%4];"
        : "=r"(r[0]), "=r"(r[1]), "=r"(r[2]), "=r"(r[3]) : "r"(addr));
}
__device__ __forceinline__ void mma16816(float* c, const uint32_t* a, uint32_t b0, uint32_t b1) {
    asm volatile("mma.sync.aligned.m16n8k16.row.col.f32.bf16.bf16.f32 "
        "{%0,%1,%2,%3}, {%4,%5,%6,%7}, {%8,%9}, {%0,%1,%2,%3};"
        : "+f"(c[0]), "+f"(c[1]), "+f"(c[2]), "+f"(c[3])
        : "r"(a[0]), "r"(a[1]), "r"(a[2]), "r"(a[3]), "r"(b0), "r"(b1));
}

// ---------------------------------------------------------------------------
// Split fp32 -> bf16 hi/lo
// ---------------------------------------------------------------------------
__global__ void split_act(const float* __restrict__ src, int n4)
{
    int i = blockIdx.x * blockDim.x + threadIdx.x;
    if (i >= n4) return;
    float4 x = ((const float4*)src)[i];
    __nv_bfloat16 h0 = __float2bfloat16(x.x), h1 = __float2bfloat16(x.y);
    __nv_bfloat16 h2 = __float2bfloat16(x.z), h3 = __float2bfloat16(x.w);
    __nv_bfloat16 l0 = __float2bfloat16(x.x - __bfloat162float(h0));
    __nv_bfloat16 l1 = __float2bfloat16(x.y - __bfloat162float(h1));
    __nv_bfloat16 l2 = __float2bfloat16(x.z - __bfloat162float(h2));
    __nv_bfloat16 l3 = __float2bfloat16(x.w - __bfloat162float(h3));
    ((__nv_bfloat162*)g_ahi)[i*2+0] = __nv_bfloat162(h0, h1);
    ((__nv_bfloat162*)g_ahi)[i*2+1] = __nv_bfloat162(h2, h3);
    ((__nv_bfloat162*)g_alo)[i*2+0] = __nv_bfloat162(l0, l1);
    ((__nv_bfloat162*)g_alo)[i*2+1] = __nv_bfloat162(l2, l3);
}

__global__ void split_w(const float* __restrict__ src, int n4)
{
    int i = blockIdx.x * blockDim.x + threadIdx.x;
    if (i >= n4) return;
    float4 x = ((const float4*)src)[i];
    __nv_bfloat16 h0 = __float2bfloat16(x.x), h1 = __float2bfloat16(x.y);
    __nv_bfloat16 h2 = __float2bfloat16(x.z), h3 = __float2bfloat16(x.w);
    __nv_bfloat16 l0 = __float2bfloat16(x.x - __bfloat162float(h0));
    __nv_bfloat16 l1 = __float2bfloat16(x.y - __bfloat162float(h1));
    __nv_bfloat16 l2 = __float2bfloat16(x.z - __bfloat162float(h2));
    __nv_bfloat16 l3 = __float2bfloat16(x.w - __bfloat162float(h3));
    ((__nv_bfloat162*)g_bhi)[i*2+0] = __nv_bfloat162(h0, h1);
    ((__nv_bfloat162*)g_bhi)[i*2+1] = __nv_bfloat162(h2, h3);
    ((__nv_bfloat162*)g_blo)[i*2+0] = __nv_bfloat162(l0, l1);
    ((__nv_bfloat162*)g_blo)[i*2+1] = __nv_bfloat162(l2, l3);
}

// g_att [B,H,T,D] -> flat [M,E] hi/lo
__global__ void gather_att_split()
{
    int i = blockIdx.x * blockDim.x + threadIdx.x;
    int m = i >> 8;
    int e4 = (i & 255) * 4;
    int bb = m >> 10, t = m & 1023, h = e4 >> 6, d = e4 & 63;
    float4 x = *(const float4*)&g_att[(((size_t)(bb * H_ + h) * T_ + t) * D_) + d];
    __nv_bfloat16 h0 = __float2bfloat16(x.x), h1 = __float2bfloat16(x.y);
    __nv_bfloat16 h2 = __float2bfloat16(x.z), h3 = __float2bfloat16(x.w);
    __nv_bfloat16 l0 = __float2bfloat16(x.x - __bfloat162float(h0));
    __nv_bfloat16 l1 = __float2bfloat16(x.y - __bfloat162float(h1));
    __nv_bfloat16 l2 = __float2bfloat16(x.z - __bfloat162float(h2));
    __nv_bfloat16 l3 = __float2bfloat16(x.w - __bfloat162float(h3));
    size_t o2 = ((size_t)m * E_ + e4) >> 1;
    ((__nv_bfloat162*)g_ahi)[o2+0] = __nv_bfloat162(h0, h1);
    ((__nv_bfloat162*)g_ahi)[o2+1] = __nv_bfloat162(h2, h3);
    ((__nv_bfloat162*)g_alo)[o2+0] = __nv_bfloat162(l0, l1);
    ((__nv_bfloat162*)g_alo)[o2+1] = __nv_bfloat162(l2, l3);
}

// ---------------------------------------------------------------------------
// HMMA GEMM: C[M,N] = A[M,K']·B[N,K']^T, K' = 3*1024 split-concat:
//   parts: 0=Ahi·Bhi, 1=Alo·Bhi, 2=Ahi·Blo.
// CTA 128x128, 8 warps (4m x 2n), warp 32x64, mma m16n8k16 bf16.
// 2-stage cp.async pipeline, K-chunk 32, smem stride 40 (conflict-free LDSM).
// mode 0/1/2 -> scatter+bias to g_qh/g_kh/g_vh; 3 -> flat out.
// ---------------------------------------------------------------------------
__global__ void __launch_bounds__(256) gemm_mma(
    const float* __restrict__ bias, float* __restrict__ out, int mode)
{
    __shared__ __align__(16) __nv_bfloat16 As[2][128][40];
    __shared__ __align__(16) __nv_bfloat16 Bs[2][128][40];

    const int tid = threadIdx.x;
    const int lane = tid & 31;
    const int wid = tid >> 5;
    const int wm = wid & 3;          // 0..3 -> m offset 32*wm
    const int wn = wid >> 2;         // 0..1 -> n offset 64*wn
    const int m0 = blockIdx.y * 128;
    const int n0 = blockIdx.x * 128;

    const uint32_t sAu = smem_u32(&As[0][0][0]);
    const uint32_t sBu = smem_u32(&Bs[0][0][0]);

    float acc[2][8][4];
    #pragma unroll
    for (int i = 0; i < 2; i++)
        #pragma unroll
        for (int j = 0; j < 8; j++)
            #pragma unroll
            for (int q = 0; q < 4; q++) acc[i][j][q] = 0.0f;

    const int lr = tid >> 2;          // 0..63 base row for loads (2 iters -> 128)
    const int lk = (tid & 3) * 8;     // 0,8,16,24

    auto issue = [&](int c, int s) {
        const __nv_bfloat16* Ap = (c < 32 || c >= 64) ? g_ahi : g_alo;
        const __nv_bfloat16* Bp = (c < 64) ? g_bhi : g_blo;
        const int koff = (c & 31) * 32;
        #pragma unroll
        for (int i = 0; i < 2; i++) {
            int row = lr + i * 64;
            uint32_t dA = sAu + (uint32_t)(((s * 128 + row) * 40 + lk) * 2);
            cp16(dA, Ap + (size_t)(m0 + row) * E_ + koff + lk);
            uint32_t dB = sBu + (uint32_t)(((s * 128 + row) * 40 + lk) * 2);
            cp16(dB, Bp + (size_t)(n0 + row) * E_ + koff + lk);
        }
    };

    const int NCHUNK = 96;
    issue(0, 0);
    CP_COMMIT();

    for (int c = 0; c < NCHUNK; c++) {
        const int s = c & 1;
        if (c + 1 < NCHUNK) {
            issue(c + 1, s ^ 1);
            CP_COMMIT();
            asm volatile("cp.async.wait_group 1;" ::: "memory");
        } else {
            asm volatile("cp.async.wait_group 0;" ::: "memory");
        }
        __syncthreads();

        #pragma unroll
        for (int ks = 0; ks < 2; ks++) {
            // A fragments: 2 x (16x16)
            uint32_t a[2][4];
            #pragma unroll
            for (int mf = 0; mf < 2; mf++) {
                int row = wm * 32 + mf * 16 + (lane & 15);
                int col = ks * 16 + (lane >> 4) * 8;
                ldsm_x4(a[mf], sAu + (uint32_t)(((s * 128 + row) * 40 + col) * 2));
            }
            // B fragments: 4 x ldsm covering 16 n-rows each
            uint32_t b[4][4];
            #pragma unroll
            for (int nf2 = 0; nf2 < 4; nf2++) {
                int row = wn * 64 + nf2 * 16 + (lane & 7) + (lane >> 4) * 8;
                int col = ks * 16 + ((lane >> 3) & 1) * 8;
                ldsm_x4(b[nf2], sBu + (uint32_t)(((s * 128 + row) * 40 + col) * 2));
            }
            #pragma unroll
            for (int mf = 0; mf < 2; mf++)
                #pragma unroll
                for (int nf2 = 0; nf2 < 4; nf2++) {
                    mma16816(acc[mf][nf2 * 2 + 0], a[mf], b[nf2][0], b[nf2][1]);
                    mma16816(acc[mf][nf2 * 2 + 1], a[mf], b[nf2][2], b[nf2][3]);
                }
        }
        __syncthreads();
    }

    // Epilogue: fragment layout m16n8: c0,c1 -> (row, 2*tig(+1)); c2,c3 -> row+8
    const int gid = lane >> 2;        // 0..7
    const int tig = lane & 3;         // 0..3
    float* O3 = out;
    #pragma unroll
    for (int mf = 0; mf < 2; mf++) {
        #pragma unroll
        for (int nf = 0; nf < 8; nf++) {
            int row = m0 + wm * 32 + mf * 16 + gid;
            int col = n0 + wn * 64 + nf * 8 + tig * 2;
            float b0 = bias[col], b1 = bias[col + 1];
            float v00 = acc[mf][nf][0] + b0, v01 = acc[mf][nf][1] + b1;
            float v10 = acc[mf][nf][2] + b0, v11 = acc[mf][nf][3] + b1;
            if (mode == 3) {
                *(float2*)&O3[(size_t)row * E_ + col] = make_float2(v00, v01);
                *(float2*)&O3[(size_t)(row + 8) * E_ + col] = make_float2(v10, v11);
            } else {
                float* O = (mode == 0) ? g_qh : (mode == 1) ? g_kh : g_vh;
                int h = col >> 6, d = col & 63;
                int bb0 = row >> 10, t0 = row & 1023;
                int rw1 = row + 8;
                int bb1 = rw1 >> 10, t1 = rw1 & 1023;
                *(float2*)&O[(((size_t)(bb0 * H_ + h) * T_ + t0) * D_) + d] = make_float2(v00, v01);
                *(float2*)&O[(((size_t)(bb1 * H_ + h) * T_ + t1) * D_) + d] = make_float2(v10, v11);
            }
        }
    }
}

// ---------------------------------------------------------------------------
// Energy: S[head,i,j] = mask(sum_d qh[i,d]*kh[j,d] * SCALE * w_j^2)  (fp32)
// ---------------------------------------------------------------------------
__global__ void __launch_bounds__(256, 2) energy_kernel(const float* __restrict__ weights)
{
    __shared__ float As[16][128];
    __shared__ float Bs[16][128];
    const int head = blockIdx.z;
    const float* A = g_qh + head * T_ * D_;
    const float* Bm = g_kh + head * T_ * D_;
    const int m0 = blockIdx.y * 128;
    const int n0 = blockIdx.x * 128;
    const int tid = threadIdx.x;
    const int tx = tid & 15, ty = tid >> 4;

    float acc[8][8];
    #pragma unroll
    for (int i = 0; i < 8; i++)
        #pragma unroll
        for (int j = 0; j < 8; j++) acc[i][j] = 0.0f;

    for (int k0 = 0; k0 < D_; k0 += 16) {
        #pragma unroll
        for (int i = 0; i < 2; i++) {
            int f = tid + i * 256;
            int row = f >> 2;
            int c4  = (f & 3) * 4;
            float4 a = *(const float4*)&A[(m0 + row) * D_ + k0 + c4];
            As[c4 + 0][row] = a.x; As[c4 + 1][row] = a.y;
            As[c4 + 2][row] = a.z; As[c4 + 3][row] = a.w;
            float4 b = *(const float4*)&Bm[(n0 + row) * D_ + k0 + c4];
            Bs[c4 + 0][row] = b.x; Bs[c4 + 1][row] = b.y;
            Bs[c4 + 2][row] = b.z; Bs[c4 + 3][row] = b.w;
        }
        __syncthreads();
        #pragma unroll
        for (int k = 0; k < 16; k++) {
            float4 a0 = *(const float4*)&As[k][ty * 8];
            float4 a1 = *(const float4*)&As[k][ty * 8 + 4];
            float4 b0 = *(const float4*)&Bs[k][tx * 8];
            float4 b1 = *(const float4*)&Bs[k][tx * 8 + 4];
            float av[8] = {a0.x, a0.y, a0.z, a0.w, a1.x, a1.y, a1.z, a1.w};
            float bv[8] = {b0.x, b0.y, b0.z, b0.w, b1.x, b1.y, b1.z, b1.w};
            #pragma unroll
            for (int i = 0; i < 8; i++)
                #pragma unroll
                for (int j = 0; j < 8; j++)
                    acc[i][j] = fmaf(av[i], bv[j], acc[i][j]);
        }
        __syncthreads();
    }

    const float* wrow = weights + (head >> 4) * T_;
    float* Srow = g_S + (size_t)head * T_ * T_;
    #pragma unroll
    for (int j = 0; j < 8; j++) {
        int n = n0 + tx * 8 + j;
        float w = wrow[n];
        bool masked = (w < WEPS_);
        float scl = SCALE_ * w * w;
        #pragma unroll
        for (int i = 0; i < 8; i++) {
            int m = m0 + ty * 8 + i;
            Srow[(size_t)m * T_ + n] = masked ? neg_inf() : acc[i][j] * scl;
        }
    }
}

// ---------------------------------------------------------------------------
// Row softmax
// ---------------------------------------------------------------------------
__global__ void softmax_kernel()
{
    const size_t row = blockIdx.x;
    float* r = g_S + row * T_;
    const int tid = threadIdx.x;
    __shared__ float red[256];

    float4 x = *(const float4*)&r[tid * 4];
    float m = fmaxf(fmaxf(x.x, x.y), fmaxf(x.z, x.w));
    red[tid] = m; __syncthreads();
    #pragma unroll
    for (int s = 128; s > 0; s >>= 1) {
        if (tid < s) red[tid] = fmaxf(red[tid], red[tid + s]);
        __syncthreads();
    }
    float rmax = red[0];
    __syncthreads();

    float e0 = __expf(x.x - rmax);
    float e1 = __expf(x.y - rmax);
    float e2 = __expf(x.z - rmax);
    float e3 = __expf(x.w - rmax);
    red[tid] = e0 + e1 + e2 + e3; __syncthreads();
    #pragma unroll
    for (int s = 128; s > 0; s >>= 1) {
        if (tid < s) red[tid] = red[tid] + red[tid + s];
        __syncthreads();
    }
    float inv = 1.0f / red[0];
    *(float4*)&r[tid * 4] = make_float4(e0 * inv, e1 * inv, e2 * inv, e3 * inv);
}

// ---------------------------------------------------------------------------
// PV: att[head,q,d] = sum_k S[head,q,k] * vh[head,k,d]  (fp32)
// ---------------------------------------------------------------------------
__global__ void __launch_bounds__(256, 2) pv_kernel()
{
    __shared__ float As[16][128];
    __shared__ float Bs[16][64];
    const int head = blockIdx.y;
    const float* S = g_S + (size_t)head * T_ * T_;
    const float* V = g_vh + head * T_ * D_;
    const int m0 = blockIdx.x * 128;
    const int tid = threadIdx.x;
    const int tx = tid & 15, ty = tid >> 4;

    float acc[8][4];
    #pragma unroll
    for (int i = 0; i < 8; i++)
        #pragma unroll
        for (int j = 0; j < 4; j++) acc[i][j] = 0.0f;

    for (int k0 = 0; k0 < T_; k0 += 16) {
        #pragma unroll
        for (int i = 0; i < 2; i++) {
            int f = tid + i * 256;
            int row = f >> 2;
            int c4  = (f & 3) * 4;
            float4 a = *(const float4*)&S[(size_t)(m0 + row) * T_ + k0 + c4];
            As[c4 + 0][row] = a.x; As[c4 + 1][row] = a.y;
            As[c4 + 2][row] = a.z; As[c4 + 3][row] = a.w;
        }
        {
            int row = tid >> 4;
            int c4  = (tid & 15) * 4;
            *(float4*)&Bs[row][c4] = *(const float4*)&V[(k0 + row) * D_ + c4];
        }
        __syncthreads();
        #pragma unroll
        for (int k = 0; k < 16; k++) {
            float4 a0 = *(const float4*)&As[k][ty * 8];
            float4 a1 = *(const float4*)&As[k][ty * 8 + 4];
            float4 b  = *(const float4*)&Bs[k][tx * 4];
            float av[8] = {a0.x, a0.y, a0.z, a0.w, a1.x, a1.y, a1.z, a1.w};
            float bv[4] = {b.x, b.y, b.z, b.w};
            #pragma unroll
            for (int i = 0; i < 8; i++)
                #pragma unroll
                for (int j = 0; j < 4; j++)
                    acc[i][j] = fmaf(av[i], bv[j], acc[i][j]);
        }
        __syncthreads();
    }

    float* O = g_att + head * T_ * D_;
    #pragma unroll
    for (int i = 0; i < 8; i++) {
        int m = m0 + ty * 8 + i;
        #pragma unroll
        for (int j = 0; j < 4; j++)
            O[m * D_ + tx * 4 + j] = acc[i][j];
    }
}

// ---------------------------------------------------------------------------
extern "C" void kernel_launch(void* const* d_in, const int* in_sizes, int n_in,
                              void* d_out, int out_size)
{
    const float* q       = (const float*)d_in[0];
    const float* k       = (const float*)d_in[1];
    const float* v       = (const float*)d_in[2];
    const float* weights = (const float*)d_in[3];
    const float* Wq      = (const float*)d_in[4];
    const float* bq      = (const float*)d_in[5];
    const float* Wk      = (const float*)d_in[6];
    const float* bk      = (const float*)d_in[7];
    const float* Wv      = (const float*)d_in[8];
    const float* bv      = (const float*)d_in[9];
    const float* Wo      = (const float*)d_in[10];
    const float* bo      = (const float*)d_in[11];
    float* out = (float*)d_out;

    const int actN4 = M_ * E_ / 4;
    const int wN4   = E_ * E_ / 4;
    dim3 blk(256);
    dim3 gg(8, 32);

    split_act<<<(actN4 + 255) / 256, blk>>>(q, actN4);
    split_w<<<(wN4 + 255) / 256, blk>>>(Wq, wN4);
    gemm_mma<<<gg, blk>>>(bq, out, 0);

    split_act<<<(actN4 + 255) / 256, blk>>>(k, actN4);
    split_w<<<(wN4 + 255) / 256, blk>>>(Wk, wN4);
    gemm_mma<<<gg, blk>>>(bk, out, 1);

    split_act<<<(actN4 + 255) / 256, blk>>>(v, actN4);
    split_w<<<(wN4 + 255) / 256, blk>>>(Wv, wN4);
    gemm_mma<<<gg, blk>>>(bv, out, 2);

    energy_kernel<<<dim3(8, 8, 64), blk>>>(weights);
    softmax_kernel<<<dim3(B_ * H_ * T_), blk>>>();
    pv_kernel<<<dim3(8, 64), blk>>>();

    gather_att_split<<<(M_ * 256 + 255) / 256, blk>>>();
    split_w<<<(wN4 + 255) / 256, blk>>>(Wo, wN4);
    gemm_mma<<<gg, blk>>>(bo, out, 3);
}

// round 10
// speedup vs baseline: 2.9822x; 2.0258x over previous
#include <cuda_runtime.h>
#include <cuda_bf16.h>
#include <cstdint>

// ---------------- Problem constants ----------------
#define B_ 4
#define T_ 1024
#define E_ 1024
#define H_ 16
#define D_ 64
#define M_ 4096              // B*T rows
#define SCALE_ 0.125f        // 1/sqrt(64)
#define WEPS_ 1e-5f
#define NEGINF_ -1e30f

// ---------------- Scratch (__device__ globals) ----------
__device__ __align__(16) float g_att[B_*H_*T_*D_];               // [head][t][64]
__device__ __align__(16) __nv_bfloat16 g_ahi[M_*E_];
__device__ __align__(16) __nv_bfloat16 g_alo[M_*E_];
__device__ __align__(16) __nv_bfloat16 g_bhi[E_*E_];
__device__ __align__(16) __nv_bfloat16 g_blo[E_*E_];
// projected Q/K: [head][t][64]; V transposed: [head][d][t]
__device__ __align__(16) __nv_bfloat16 g_qhh[64*T_*D_];
__device__ __align__(16) __nv_bfloat16 g_qhl[64*T_*D_];
__device__ __align__(16) __nv_bfloat16 g_khh[64*T_*D_];
__device__ __align__(16) __nv_bfloat16 g_khl[64*T_*D_];
__device__ __align__(16) __nv_bfloat16 g_vhh[64*D_*T_];
__device__ __align__(16) __nv_bfloat16 g_vhl[64*D_*T_];

__device__ __forceinline__ uint32_t smem_u32(const void* p) {
    uint32_t a;
    asm("{ .reg .u64 t; cvta.to.shared.u64 t, %1; cvt.u32.u64 %0, t; }" : "=r"(a) : "l"(p));
    return a;
}
__device__ __forceinline__ void cp16(uint32_t dst, const void* src) {
    asm volatile("cp.async.ca.shared.global [%0], [%1], 16;" :: "r"(dst), "l"(src));
}
#define CP_COMMIT() asm volatile("cp.async.commit_group;" ::: "memory")

__device__ __forceinline__ void ldsm_x4(uint32_t* r, uint32_t addr) {
    asm volatile("ldmatrix.sync.aligned.m8n8.x4.shared.b16 {%0,%1,%2,%3}, [%4];"
        : "=r"(r[0]), "=r"(r[1]), "=r"(r[2]), "=r"(r[3]) : "r"(addr));
}
__device__ __forceinline__ void mma16816(float* c, const uint32_t* a, uint32_t b0, uint32_t b1) {
    asm volatile("mma.sync.aligned.m16n8k16.row.col.f32.bf16.bf16.f32 "
        "{%0,%1,%2,%3}, {%4,%5,%6,%7}, {%8,%9}, {%0,%1,%2,%3};"
        : "+f"(c[0]), "+f"(c[1]), "+f"(c[2]), "+f"(c[3])
        : "r"(a[0]), "r"(a[1]), "r"(a[2]), "r"(a[3]), "r"(b0), "r"(b1));
}
__device__ __forceinline__ uint32_t pack_bf2(float lo, float hi) {
    __nv_bfloat162 t(__float2bfloat16(lo), __float2bfloat16(hi));  // .x = low half
    return *(uint32_t*)&t;
}

// ---------------------------------------------------------------------------
// fp32 -> bf16 hi/lo splits
// ---------------------------------------------------------------------------
__global__ void split_act(const float* __restrict__ src, int n4)
{
    int i = blockIdx.x * blockDim.x + threadIdx.x;
    if (i >= n4) return;
    float4 x = ((const float4*)src)[i];
    __nv_bfloat16 h0 = __float2bfloat16(x.x), h1 = __float2bfloat16(x.y);
    __nv_bfloat16 h2 = __float2bfloat16(x.z), h3 = __float2bfloat16(x.w);
    __nv_bfloat16 l0 = __float2bfloat16(x.x - __bfloat162float(h0));
    __nv_bfloat16 l1 = __float2bfloat16(x.y - __bfloat162float(h1));
    __nv_bfloat16 l2 = __float2bfloat16(x.z - __bfloat162float(h2));
    __nv_bfloat16 l3 = __float2bfloat16(x.w - __bfloat162float(h3));
    ((__nv_bfloat162*)g_ahi)[i*2+0] = __nv_bfloat162(h0, h1);
    ((__nv_bfloat162*)g_ahi)[i*2+1] = __nv_bfloat162(h2, h3);
    ((__nv_bfloat162*)g_alo)[i*2+0] = __nv_bfloat162(l0, l1);
    ((__nv_bfloat162*)g_alo)[i*2+1] = __nv_bfloat162(l2, l3);
}

__global__ void split_w(const float* __restrict__ src, int n4)
{
    int i = blockIdx.x * blockDim.x + threadIdx.x;
    if (i >= n4) return;
    float4 x = ((const float4*)src)[i];
    __nv_bfloat16 h0 = __float2bfloat16(x.x), h1 = __float2bfloat16(x.y);
    __nv_bfloat16 h2 = __float2bfloat16(x.z), h3 = __float2bfloat16(x.w);
    __nv_bfloat16 l0 = __float2bfloat16(x.x - __bfloat162float(h0));
    __nv_bfloat16 l1 = __float2bfloat16(x.y - __bfloat162float(h1));
    __nv_bfloat16 l2 = __float2bfloat16(x.z - __bfloat162float(h2));
    __nv_bfloat16 l3 = __float2bfloat16(x.w - __bfloat162float(h3));
    ((__nv_bfloat162*)g_bhi)[i*2+0] = __nv_bfloat162(h0, h1);
    ((__nv_bfloat162*)g_bhi)[i*2+1] = __nv_bfloat162(h2, h3);
    ((__nv_bfloat162*)g_blo)[i*2+0] = __nv_bfloat162(l0, l1);
    ((__nv_bfloat162*)g_blo)[i*2+1] = __nv_bfloat162(l2, l3);
}

// g_att [head][t][64] -> flat [M,E] hi/lo
__global__ void gather_att_split()
{
    int i = blockIdx.x * blockDim.x + threadIdx.x;
    int m = i >> 8;
    int e4 = (i & 255) * 4;
    int bb = m >> 10, t = m & 1023, h = e4 >> 6, d = e4 & 63;
    float4 x = *(const float4*)&g_att[(((size_t)(bb * H_ + h) * T_ + t) * D_) + d];
    __nv_bfloat16 h0 = __float2bfloat16(x.x), h1 = __float2bfloat16(x.y);
    __nv_bfloat16 h2 = __float2bfloat16(x.z), h3 = __float2bfloat16(x.w);
    __nv_bfloat16 l0 = __float2bfloat16(x.x - __bfloat162float(h0));
    __nv_bfloat16 l1 = __float2bfloat16(x.y - __bfloat162float(h1));
    __nv_bfloat16 l2 = __float2bfloat16(x.z - __bfloat162float(h2));
    __nv_bfloat16 l3 = __float2bfloat16(x.w - __bfloat162float(h3));
    size_t o2 = ((size_t)m * E_ + e4) >> 1;
    ((__nv_bfloat162*)g_ahi)[o2+0] = __nv_bfloat162(h0, h1);
    ((__nv_bfloat162*)g_ahi)[o2+1] = __nv_bfloat162(h2, h3);
    ((__nv_bfloat162*)g_alo)[o2+0] = __nv_bfloat162(l0, l1);
    ((__nv_bfloat162*)g_alo)[o2+1] = __nv_bfloat162(l2, l3);
}

// ---------------------------------------------------------------------------
// HMMA GEMM: C = A·B^T over K'=3072 (hi/lo 3-term). CTA 128x128, 8 warps.
// mode 0: ->g_qhh/l [head][t][64]   mode 1: ->g_khh/l
// mode 2: ->g_vhh/l [head][d][t] (transposed)   mode 3: fp32 flat out + bias
// ---------------------------------------------------------------------------
__global__ void __launch_bounds__(256) gemm_mma(
    const float* __restrict__ bias, float* __restrict__ out, int mode)
{
    __shared__ __align__(16) __nv_bfloat16 As[2][128][40];
    __shared__ __align__(16) __nv_bfloat16 Bs[2][128][40];

    const int tid = threadIdx.x;
    const int lane = tid & 31;
    const int wid = tid >> 5;
    const int wm = wid & 3;
    const int wn = wid >> 2;
    const int m0 = blockIdx.y * 128;
    const int n0 = blockIdx.x * 128;

    const uint32_t sAu = smem_u32(&As[0][0][0]);
    const uint32_t sBu = smem_u32(&Bs[0][0][0]);

    float acc[2][8][4];
    #pragma unroll
    for (int i = 0; i < 2; i++)
        #pragma unroll
        for (int j = 0; j < 8; j++)
            #pragma unroll
            for (int q = 0; q < 4; q++) acc[i][j][q] = 0.0f;

    const int lr = tid >> 2;
    const int lk = (tid & 3) * 8;

    auto issue = [&](int c, int s) {
        const __nv_bfloat16* Ap = (c < 32 || c >= 64) ? g_ahi : g_alo;
        const __nv_bfloat16* Bp = (c < 64) ? g_bhi : g_blo;
        const int koff = (c & 31) * 32;
        #pragma unroll
        for (int i = 0; i < 2; i++) {
            int row = lr + i * 64;
            uint32_t dA = sAu + (uint32_t)(((s * 128 + row) * 40 + lk) * 2);
            cp16(dA, Ap + (size_t)(m0 + row) * E_ + koff + lk);
            uint32_t dB = sBu + (uint32_t)(((s * 128 + row) * 40 + lk) * 2);
            cp16(dB, Bp + (size_t)(n0 + row) * E_ + koff + lk);
        }
    };

    const int NCHUNK = 96;
    issue(0, 0);
    CP_COMMIT();

    for (int c = 0; c < NCHUNK; c++) {
        const int s = c & 1;
        if (c + 1 < NCHUNK) {
            issue(c + 1, s ^ 1);
            CP_COMMIT();
            asm volatile("cp.async.wait_group 1;" ::: "memory");
        } else {
            asm volatile("cp.async.wait_group 0;" ::: "memory");
        }
        __syncthreads();

        #pragma unroll
        for (int ks = 0; ks < 2; ks++) {
            uint32_t a[2][4];
            #pragma unroll
            for (int mf = 0; mf < 2; mf++) {
                int row = wm * 32 + mf * 16 + (lane & 15);
                int col = ks * 16 + (lane >> 4) * 8;
                ldsm_x4(a[mf], sAu + (uint32_t)(((s * 128 + row) * 40 + col) * 2));
            }
            uint32_t b[4][4];
            #pragma unroll
            for (int nf2 = 0; nf2 < 4; nf2++) {
                int row = wn * 64 + nf2 * 16 + (lane & 7) + (lane >> 4) * 8;
                int col = ks * 16 + ((lane >> 3) & 1) * 8;
                ldsm_x4(b[nf2], sBu + (uint32_t)(((s * 128 + row) * 40 + col) * 2));
            }
            #pragma unroll
            for (int mf = 0; mf < 2; mf++)
                #pragma unroll
                for (int nf2 = 0; nf2 < 4; nf2++) {
                    mma16816(acc[mf][nf2 * 2 + 0], a[mf], b[nf2][0], b[nf2][1]);
                    mma16816(acc[mf][nf2 * 2 + 1], a[mf], b[nf2][2], b[nf2][3]);
                }
        }
        __syncthreads();
    }

    const int gid = lane >> 2;
    const int tig = lane & 3;
    #pragma unroll
    for (int mf = 0; mf < 2; mf++) {
        #pragma unroll
        for (int nf = 0; nf < 8; nf++) {
            int row = m0 + wm * 32 + mf * 16 + gid;
            int col = n0 + wn * 64 + nf * 8 + tig * 2;
            if (mode == 3) {
                float b0 = bias[col], b1 = bias[col + 1];
                *(float2*)&out[(size_t)row * E_ + col] =
                    make_float2(acc[mf][nf][0] + b0, acc[mf][nf][1] + b1);
                *(float2*)&out[(size_t)(row + 8) * E_ + col] =
                    make_float2(acc[mf][nf][2] + b0, acc[mf][nf][3] + b1);
            } else {
                float b0 = bias[col], b1 = bias[col + 1];
                float v00 = acc[mf][nf][0] + b0, v01 = acc[mf][nf][1] + b1;
                float v10 = acc[mf][nf][2] + b0, v11 = acc[mf][nf][3] + b1;
                int h = (row >> 10) * 16 + (col >> 6);
                int t0 = row & 1023, d = col & 63;
                __nv_bfloat16 h00 = __float2bfloat16(v00), h01 = __float2bfloat16(v01);
                __nv_bfloat16 h10 = __float2bfloat16(v10), h11 = __float2bfloat16(v11);
                __nv_bfloat16 l00 = __float2bfloat16(v00 - __bfloat162float(h00));
                __nv_bfloat16 l01 = __float2bfloat16(v01 - __bfloat162float(h01));
                __nv_bfloat16 l10 = __float2bfloat16(v10 - __bfloat162float(h10));
                __nv_bfloat16 l11 = __float2bfloat16(v11 - __bfloat162float(h11));
                if (mode == 2) {
                    size_t base = ((size_t)h * 64 + d) * 1024;
                    g_vhh[base + t0] = h00;          g_vhh[base + 1024 + t0] = h01;
                    g_vhh[base + t0 + 8] = h10;      g_vhh[base + 1024 + t0 + 8] = h11;
                    g_vhl[base + t0] = l00;          g_vhl[base + 1024 + t0] = l01;
                    g_vhl[base + t0 + 8] = l10;      g_vhl[base + 1024 + t0 + 8] = l11;
                } else {
                    __nv_bfloat16* Hh = (mode == 0) ? g_qhh : g_khh;
                    __nv_bfloat16* Hl = (mode == 0) ? g_qhl : g_khl;
                    size_t i0 = ((size_t)h * 1024 + t0) * 64 + d;
                    size_t i1 = ((size_t)h * 1024 + t0 + 8) * 64 + d;
                    *(__nv_bfloat162*)(Hh + i0) = __nv_bfloat162(h00, h01);
                    *(__nv_bfloat162*)(Hl + i0) = __nv_bfloat162(l00, l01);
                    *(__nv_bfloat162*)(Hh + i1) = __nv_bfloat162(h10, h11);
                    *(__nv_bfloat162*)(Hl + i1) = __nv_bfloat162(l10, l11);
                }
            }
        }
    }
}

// ---------------------------------------------------------------------------
// Fused flash attention. grid (8 q-tiles, 64 heads), 256 threads.
// Warp w owns q-rows [16w,16w+16). S=QK^T (3-term hi/lo HMMA), scale*w^2+mask,
// online softmax in regs, P hi/lo in regs, O += P·V (3-term HMMA).
// ---------------------------------------------------------------------------
#define KSTR 72
#define VSTR 136
#define KHI_OFF 0
#define KLO_OFF 18432
#define VHI_OFF 36864
#define VLO_OFF 54272
#define STAGE_SZ 71680
#define SW_OFF  143360
#define FLASH_SMEM (SW_OFF + 1024)

__global__ void __launch_bounds__(256) flash_kernel(const float* __restrict__ weights)
{
    extern __shared__ char sm[];
    const int tid = threadIdx.x, lane = tid & 31, wid = tid >> 5;
    const int head = blockIdx.y, m0 = blockIdx.x * 128;
    const int batch = head >> 4;
    const uint32_t smb = smem_u32(sm);

    // ---- preload Q (hi->KHI region, lo->KLO region of stage 0), ldsm to regs
    #pragma unroll
    for (int i = 0; i < 4; i++) {
        int task = tid + i * 256;
        int r = task >> 3, ch = task & 7;
        size_t src = ((size_t)head * 1024 + m0 + r) * 64 + ch * 8;
        cp16(smb + KHI_OFF + r * 144 + ch * 16, g_qhh + src);
        cp16(smb + KLO_OFF + r * 144 + ch * 16, g_qhl + src);
    }
    CP_COMMIT();
    asm volatile("cp.async.wait_group 0;" ::: "memory");
    __syncthreads();

    uint32_t qhi[4][4], qlo[4][4];
    {
        int row = wid * 16 + (lane & 15);
        #pragma unroll
        for (int kc = 0; kc < 4; kc++) {
            int col = kc * 16 + (lane >> 4) * 8;
            ldsm_x4(qhi[kc], smb + KHI_OFF + (uint32_t)((row * KSTR + col) * 2));
            ldsm_x4(qlo[kc], smb + KLO_OFF + (uint32_t)((row * KSTR + col) * 2));
        }
    }
    __syncthreads();

    auto issue = [&](int kt, int s) {
        uint32_t base = smb + s * STAGE_SZ;
        int k0 = kt * 128;
        #pragma unroll
        for (int i = 0; i < 4; i++) {
            int task = tid + i * 256;
            int r = task >> 3, ch = task & 7;
            size_t src = ((size_t)head * 1024 + k0 + r) * 64 + ch * 8;
            cp16(base + KHI_OFF + r * 144 + ch * 16, g_khh + src);
            cp16(base + KLO_OFF + r * 144 + ch * 16, g_khl + src);
        }
        #pragma unroll
        for (int i = 0; i < 4; i++) {
            int task = tid + i * 256;
            int r = task >> 4, ch = task & 15;
            size_t src = ((size_t)head * 64 + r) * 1024 + k0 + ch * 8;
            cp16(base + VHI_OFF + r * 272 + ch * 16, g_vhh + src);
            cp16(base + VLO_OFF + r * 272 + ch * 16, g_vhl + src);
        }
        if (tid < 128) {
            float w = weights[(size_t)batch * 1024 + k0 + tid];
            float scl = (w < WEPS_) ? -1.0f : SCALE_ * w * w;
            *(float*)(sm + SW_OFF + s * 512 + tid * 4) = scl;
        }
    };

    const int gid = lane >> 2, tig = lane & 3;
    const int brow = (lane & 7) + ((lane >> 4) << 3);
    const int bcol = ((lane >> 3) & 1) * 8;

    float m_st[2] = {NEGINF_, NEGINF_};
    float l_st[2] = {0.0f, 0.0f};
    float oacc[8][4];
    #pragma unroll
    for (int i = 0; i < 8; i++)
        #pragma unroll
        for (int j = 0; j < 4; j++) oacc[i][j] = 0.0f;

    issue(0, 0);
    CP_COMMIT();

    for (int kt = 0; kt < 8; kt++) {
        const int s = kt & 1;
        if (kt + 1 < 8) {
            issue(kt + 1, s ^ 1);
            CP_COMMIT();
            asm volatile("cp.async.wait_group 1;" ::: "memory");
        } else {
            asm volatile("cp.async.wait_group 0;" ::: "memory");
        }
        __syncthreads();

        const uint32_t kb = smb + s * STAGE_SZ;
        float sacc[16][4];
        #pragma unroll
        for (int nb = 0; nb < 16; nb++)
            #pragma unroll
            for (int q = 0; q < 4; q++) sacc[nb][q] = 0.0f;

        // ---- S = Q·K^T (3 terms)
        #pragma unroll
        for (int kc = 0; kc < 4; kc++) {
            #pragma unroll
            for (int nf2 = 0; nf2 < 8; nf2++) {
                uint32_t b[4];
                int row = nf2 * 16 + brow;
                int col = kc * 16 + bcol;
                ldsm_x4(b, kb + KHI_OFF + (uint32_t)((row * KSTR + col) * 2));
                mma16816(sacc[2*nf2],   qhi[kc], b[0], b[1]);
                mma16816(sacc[2*nf2+1], qhi[kc], b[2], b[3]);
                mma16816(sacc[2*nf2],   qlo[kc], b[0], b[1]);
                mma16816(sacc[2*nf2+1], qlo[kc], b[2], b[3]);
                ldsm_x4(b, kb + KLO_OFF + (uint32_t)((row * KSTR + col) * 2));
                mma16816(sacc[2*nf2],   qhi[kc], b[0], b[1]);
                mma16816(sacc[2*nf2+1], qhi[kc], b[2], b[3]);
            }
        }

        // ---- scale * w^2, mask, row max
        const float* sw = (const float*)(sm + SW_OFF + s * 512);
        float mx0 = NEGINF_, mx1 = NEGINF_;
        #pragma unroll
        for (int nb = 0; nb < 16; nb++) {
            float sc0 = sw[nb * 8 + tig * 2];
            float sc1 = sw[nb * 8 + tig * 2 + 1];
            float v0 = (sc0 < 0.f) ? NEGINF_ : sacc[nb][0] * sc0;
            float v1 = (sc1 < 0.f) ? NEGINF_ : sacc[nb][1] * sc1;
            float v2 = (sc0 < 0.f) ? NEGINF_ : sacc[nb][2] * sc0;
            float v3 = (sc1 < 0.f) ? NEGINF_ : sacc[nb][3] * sc1;
            sacc[nb][0] = v0; sacc[nb][1] = v1; sacc[nb][2] = v2; sacc[nb][3] = v3;
            mx0 = fmaxf(mx0, fmaxf(v0, v1));
            mx1 = fmaxf(mx1, fmaxf(v2, v3));
        }
        mx0 = fmaxf(mx0, __shfl_xor_sync(0xffffffffu, mx0, 1));
        mx0 = fmaxf(mx0, __shfl_xor_sync(0xffffffffu, mx0, 2));
        mx1 = fmaxf(mx1, __shfl_xor_sync(0xffffffffu, mx1, 1));
        mx1 = fmaxf(mx1, __shfl_xor_sync(0xffffffffu, mx1, 2));

        float mn0 = fmaxf(m_st[0], mx0), mn1 = fmaxf(m_st[1], mx1);
        float al0 = (m_st[0] == mn0) ? 1.0f : __expf(m_st[0] - mn0);
        float al1 = (m_st[1] == mn1) ? 1.0f : __expf(m_st[1] - mn1);
        float ms0 = (mn0 <= -1e29f) ? 0.0f : mn0;
        float ms1 = (mn1 <= -1e29f) ? 0.0f : mn1;

        // ---- p = exp(s - m), row sums
        float sum0 = 0.f, sum1 = 0.f;
        #pragma unroll
        for (int nb = 0; nb < 16; nb++) {
            float p0 = __expf(fmaxf(sacc[nb][0] - ms0, -80.f));
            float p1 = __expf(fmaxf(sacc[nb][1] - ms0, -80.f));
            float p2 = __expf(fmaxf(sacc[nb][2] - ms1, -80.f));
            float p3 = __expf(fmaxf(sacc[nb][3] - ms1, -80.f));
            sacc[nb][0] = p0; sacc[nb][1] = p1; sacc[nb][2] = p2; sacc[nb][3] = p3;
            sum0 += p0 + p1; sum1 += p2 + p3;
        }
        sum0 += __shfl_xor_sync(0xffffffffu, sum0, 1);
        sum0 += __shfl_xor_sync(0xffffffffu, sum0, 2);
        sum1 += __shfl_xor_sync(0xffffffffu, sum1, 1);
        sum1 += __shfl_xor_sync(0xffffffffu, sum1, 2);

        l_st[0] = l_st[0] * al0 + sum0;
        l_st[1] = l_st[1] * al1 + sum1;
        m_st[0] = mn0; m_st[1] = mn1;

        #pragma unroll
        for (int nb = 0; nb < 8; nb++) {
            oacc[nb][0] *= al0; oacc[nb][1] *= al0;
            oacc[nb][2] *= al1; oacc[nb][3] *= al1;
        }

        // ---- O += P·V (3 terms, P hi/lo packed from registers)
        #pragma unroll
        for (int kc = 0; kc < 8; kc++) {
            uint32_t aphi[4], aplo[4];
            #pragma unroll
            for (int half = 0; half < 2; half++) {
                float p0 = sacc[2*kc + half][0], p1 = sacc[2*kc + half][1];
                float p2 = sacc[2*kc + half][2], p3 = sacc[2*kc + half][3];
                __nv_bfloat16 h0 = __float2bfloat16(p0), h1 = __float2bfloat16(p1);
                __nv_bfloat16 h2 = __float2bfloat16(p2), h3 = __float2bfloat16(p3);
                float r0 = p0 - __bfloat162float(h0), r1 = p1 - __bfloat162float(h1);
                float r2 = p2 - __bfloat162float(h2), r3 = p3 - __bfloat162float(h3);
                __nv_bfloat162 th0(h0, h1), th1(h2, h3);
                aphi[2*half + 0] = *(uint32_t*)&th0;
                aphi[2*half + 1] = *(uint32_t*)&th1;
                aplo[2*half + 0] = pack_bf2(r0, r1);
                aplo[2*half + 1] = pack_bf2(r2, r3);
            }
            #pragma unroll
            for (int nf2 = 0; nf2 < 4; nf2++) {
                uint32_t b[4];
                int row = nf2 * 16 + brow;
                int col = kc * 16 + bcol;
                ldsm_x4(b, kb + VHI_OFF + (uint32_t)((row * VSTR + col) * 2));
                mma16816(oacc[2*nf2],   aphi, b[0], b[1]);
                mma16816(oacc[2*nf2+1], aphi, b[2], b[3]);
                mma16816(oacc[2*nf2],   aplo, b[0], b[1]);
                mma16816(oacc[2*nf2+1], aplo, b[2], b[3]);
                ldsm_x4(b, kb + VLO_OFF + (uint32_t)((row * VSTR + col) * 2));
                mma16816(oacc[2*nf2],   aphi, b[0], b[1]);
                mma16816(oacc[2*nf2+1], aphi, b[2], b[3]);
            }
        }
        __syncthreads();
    }

    // ---- normalize & write
    float inv0 = 1.0f / l_st[0], inv1 = 1.0f / l_st[1];
    int r0 = m0 + wid * 16 + gid;
    #pragma unroll
    for (int nb = 0; nb < 8; nb++) {
        int col = nb * 8 + tig * 2;
        *(float2*)&g_att[((size_t)head * 1024 + r0) * 64 + col] =
            make_float2(oacc[nb][0] * inv0, oacc[nb][1] * inv0);
        *(float2*)&g_att[((size_t)head * 1024 + r0 + 8) * 64 + col] =
            make_float2(oacc[nb][2] * inv1, oacc[nb][3] * inv1);
    }
}

// ---------------------------------------------------------------------------
extern "C" void kernel_launch(void* const* d_in, const int* in_sizes, int n_in,
                              void* d_out, int out_size)
{
    const float* q       = (const float*)d_in[0];
    const float* k       = (const float*)d_in[1];
    const float* v       = (const float*)d_in[2];
    const float* weights = (const float*)d_in[3];
    const float* Wq      = (const float*)d_in[4];
    const float* bq      = (const float*)d_in[5];
    const float* Wk      = (const float*)d_in[6];
    const float* bk      = (const float*)d_in[7];
    const float* Wv      = (const float*)d_in[8];
    const float* bv      = (const float*)d_in[9];
    const float* Wo      = (const float*)d_in[10];
    const float* bo      = (const float*)d_in[11];
    float* out = (float*)d_out;

    const int actN4 = M_ * E_ / 4;
    const int wN4   = E_ * E_ / 4;
    dim3 blk(256);
    dim3 gg(8, 32);

    cudaFuncSetAttribute(flash_kernel, cudaFuncAttributeMaxDynamicSharedMemorySize, FLASH_SMEM);

    split_act<<<(actN4 + 255) / 256, blk>>>(q, actN4);
    split_w<<<(wN4 + 255) / 256, blk>>>(Wq, wN4);
    gemm_mma<<<gg, blk>>>(bq, out, 0);

    split_act<<<(actN4 + 255) / 256, blk>>>(k, actN4);
    split_w<<<(wN4 + 255) / 256, blk>>>(Wk, wN4);
    gemm_mma<<<gg, blk>>>(bk, out, 1);

    split_act<<<(actN4 + 255) / 256, blk>>>(v, actN4);
    split_w<<<(wN4 + 255) / 256, blk>>>(Wv, wN4);
    gemm_mma<<<gg, blk>>>(bv, out, 2);

    flash_kernel<<<dim3(8, 64), blk, FLASH_SMEM>>>(weights);

    gather_att_split<<<(M_ * 256 + 255) / 256, blk>>>();
    split_w<<<(wN4 + 255) / 256, blk>>>(Wo, wN4);
    gemm_mma<<<gg, blk>>>(bo, out, 3);
}